// round 2
// baseline (speedup 1.0000x reference)
#include <cuda_runtime.h>
#include <cstdint>
#include <cstddef>

#define NB 16384
#define NV 1024
#define NH 256
#define KSTEPS 8
#define GW_ELEMS (NH*NV)          // 262144
#define OUT_VB_OFF GW_ELEMS       // 262144
#define OUT_HB_OFF (GW_ELEMS+NV)  // 263168
#define OUT_TOTAL (GW_ELEMS+NV+NH) // 263424

// ---------------- static scratch (no allocations allowed) ----------------
__device__ float g_v[NB*NV];        // current visible state (binary as float)
__device__ float g_h[NB*NH];        // hidden state (binary as float)
__device__ float g_prev[NB*NV];     // pre-activation for visible
__device__ float g_preh[NB*NH];     // pre-activation hidden; later pre_k -> a_k
__device__ float g_preh0[NB*NH];    // pre-activation for batch; later a_0
__device__ float g_invn[NB];
__device__ float g_gw_part[8*GW_ELEMS];
__device__ float g_vb_part[32*NV];
__device__ float g_hb_part[32*NH];

// ---------------- threefry2x32 (Random123 / JAX exact, 20 rounds) ----------------
__host__ __device__ __forceinline__ void threefry2x32(
    uint32_t k0, uint32_t k1, uint32_t c0, uint32_t c1,
    uint32_t& o0, uint32_t& o1)
{
    uint32_t k2 = k0 ^ k1 ^ 0x1BD11BDAu;
    uint32_t x0 = c0 + k0, x1 = c1 + k1;
#define TF_R(r) { x0 += x1; x1 = (x1 << (r)) | (x1 >> (32 - (r))); x1 ^= x0; }
    TF_R(13) TF_R(15) TF_R(26) TF_R(6)
    x0 += k1; x1 += k2 + 1u;
    TF_R(17) TF_R(29) TF_R(16) TF_R(24)
    x0 += k2; x1 += k0 + 2u;
    TF_R(13) TF_R(15) TF_R(26) TF_R(6)
    x0 += k0; x1 += k1 + 3u;
    TF_R(17) TF_R(29) TF_R(16) TF_R(24)
    x0 += k1; x1 += k2 + 4u;
    TF_R(13) TF_R(15) TF_R(26) TF_R(6)
    x0 += k2; x1 += k0 + 5u;
#undef TF_R
    o0 = x0; o1 = x1;
}

__device__ __forceinline__ float tf_uniform(uint32_t bits) {
    // JAX: bitcast((bits >> 9) | 0x3f800000) - 1.0  in [0,1)
    return __uint_as_float((bits >> 9) | 0x3f800000u) - 1.0f;
}
__device__ __forceinline__ float sigmoid_f(float x) {
    return 1.0f / (1.0f + expf(-x));
}

// ---------------- GEMM: C[M,NH] = A[M,NV] * W[NH,NV]^T + bias ----------------
// BM=128, BN=64, BK=16, 256 threads, 8x4 per thread. M=16384, K=1024 fixed.
__global__ __launch_bounds__(256) void gemm_nt_kernel(
    const float* __restrict__ A, const float* __restrict__ Wm,
    const float* __restrict__ bias, float* __restrict__ C)
{
    const int K = NV;
    __shared__ float As[16*132];
    __shared__ float Bs[16*68];
    int m0 = blockIdx.x * 128;
    int n0 = blockIdx.y * 64;
    int tid = threadIdx.x;
    int tx = tid & 15, ty = tid >> 4;
    int lrow = tid >> 2;            // 0..63
    int lcol = (tid & 3) << 2;      // 0,4,8,12

    float acc[8][4];
#pragma unroll
    for (int i = 0; i < 8; i++)
#pragma unroll
        for (int j = 0; j < 4; j++) acc[i][j] = 0.0f;

    for (int k0 = 0; k0 < K; k0 += 16) {
        float4 a0 = *(const float4*)(A + (size_t)(m0 + lrow) * K + k0 + lcol);
        float4 a1 = *(const float4*)(A + (size_t)(m0 + lrow + 64) * K + k0 + lcol);
        float4 b0 = *(const float4*)(Wm + (size_t)(n0 + lrow) * K + k0 + lcol);
        As[(lcol+0)*132 + lrow] = a0.x; As[(lcol+1)*132 + lrow] = a0.y;
        As[(lcol+2)*132 + lrow] = a0.z; As[(lcol+3)*132 + lrow] = a0.w;
        As[(lcol+0)*132 + lrow+64] = a1.x; As[(lcol+1)*132 + lrow+64] = a1.y;
        As[(lcol+2)*132 + lrow+64] = a1.z; As[(lcol+3)*132 + lrow+64] = a1.w;
        Bs[(lcol+0)*68 + lrow] = b0.x; Bs[(lcol+1)*68 + lrow] = b0.y;
        Bs[(lcol+2)*68 + lrow] = b0.z; Bs[(lcol+3)*68 + lrow] = b0.w;
        __syncthreads();
#pragma unroll
        for (int kk = 0; kk < 16; kk++) {
            float rm[8], rn[4];
#pragma unroll
            for (int i = 0; i < 8; i++) rm[i] = As[kk*132 + ty*8 + i];
#pragma unroll
            for (int j = 0; j < 4; j++) rn[j] = Bs[kk*68 + tx*4 + j];
#pragma unroll
            for (int i = 0; i < 8; i++)
#pragma unroll
                for (int j = 0; j < 4; j++)
                    acc[i][j] = fmaf(rm[i], rn[j], acc[i][j]);
        }
        __syncthreads();
    }
#pragma unroll
    for (int i = 0; i < 8; i++) {
        int m = m0 + ty*8 + i;
#pragma unroll
        for (int j = 0; j < 4; j++) {
            int n = n0 + tx*4 + j;
            C[(size_t)m * NH + n] = acc[i][j] + bias[n];
        }
    }
}

// ---------------- sampler (JAX partitionable threefry) ----------------
// bits[i] = o0 ^ o1 of threefry2x32(key, c0 = 0 (= i>>32), c1 = i)
// out[i]  = (uniform(bits[i]) < sigmoid(pre[i])) ? 1 : 0
__global__ __launch_bounds__(256) void sample_kernel(
    const float* __restrict__ pre, float* __restrict__ out,
    uint32_t k0, uint32_t k1, int total)
{
    int e = (blockIdx.x * blockDim.x + threadIdx.x) * 2;
    if (e >= total) return;
    uint32_t a0, a1, b0, b1;
    threefry2x32(k0, k1, 0u, (uint32_t)e,       a0, a1);
    threefry2x32(k0, k1, 0u, (uint32_t)(e + 1), b0, b1);
    float u0 = tf_uniform(a0 ^ a1);
    float u1 = tf_uniform(b0 ^ b1);
    out[e]     = (u0 < sigmoid_f(pre[e]))     ? 1.0f : 0.0f;
    out[e + 1] = (u1 < sigmoid_f(pre[e + 1])) ? 1.0f : 0.0f;
}

// ---------------- sparse h @ W + vb (h ~0.7% dense) ----------------
// one warp per sample; acc over 1024 visible units in 32 regs/lane
__global__ __launch_bounds__(256) void spmm_hW_kernel(
    const float* __restrict__ h, const float* __restrict__ Wm,
    const float* __restrict__ vb, float* __restrict__ prev)
{
    int warp = (blockIdx.x * blockDim.x + threadIdx.x) >> 5;
    int lane = threadIdx.x & 31;
    if (warp >= NB) return;
    const float* hr = h + (size_t)warp * NH;
    float acc[32];
#pragma unroll
    for (int t = 0; t < 32; t++) acc[t] = vb[t*32 + lane];
#pragma unroll
    for (int g = 0; g < 8; g++) {
        float hv = hr[g*32 + lane];
        unsigned mask = __ballot_sync(0xffffffffu, hv != 0.0f);
        while (mask) {
            int bit = __ffs(mask) - 1; mask &= mask - 1;
            const float* wr = Wm + (size_t)(g*32 + bit) * NV;
#pragma unroll
            for (int t = 0; t < 32; t++) acc[t] += wr[t*32 + lane];
        }
    }
    float* outp = prev + (size_t)warp * NV;
#pragma unroll
    for (int t = 0; t < 32; t++) outp[t*32 + lane] = acc[t];
}

// ---------------- inv_norm: exp(-(vk.vb + sum softplus(pre_k))) / NB ----------------
__global__ __launch_bounds__(256) void invn_kernel(
    const float* __restrict__ prek, const float* __restrict__ vk,
    const float* __restrict__ vb, float* __restrict__ invn)
{
    int warp = (blockIdx.x * blockDim.x + threadIdx.x) >> 5;
    int lane = threadIdx.x & 31;
    if (warp >= NB) return;
    float s = 0.0f;
    const float* pr = prek + (size_t)warp * NH;
#pragma unroll
    for (int t = 0; t < 8; t++) {
        float x = pr[t*32 + lane];
        s += fmaxf(x, 0.0f) + log1pf(expf(-fabsf(x)));   // softplus
    }
    const float* vr = vk + (size_t)warp * NV;
#pragma unroll
    for (int t = 0; t < 32; t++) s = fmaf(vr[t*32 + lane], vb[t*32 + lane], s);
#pragma unroll
    for (int o = 16; o > 0; o >>= 1) s += __shfl_xor_sync(0xffffffffu, s, o);
    if (lane == 0) invn[warp] = expf(-s) * (1.0f / (float)NB);
}

// ---------------- a = invn[b] * sigmoid(pre), in place on [NB,NH] ----------------
__global__ __launch_bounds__(256) void atrans_kernel(
    float* __restrict__ a, const float* __restrict__ invn)
{
    int i = blockIdx.x * blockDim.x + threadIdx.x;
    if (i >= NB * NH) return;
    int b = i >> 8;
    a[i] = invn[b] * sigmoid_f(a[i]);
}

// ---------------- g_W split-K GEMM: part[s][h][v] += ak^T vk - a0^T v0 ----------------
// M=NH(64/block), N=NV(64/block), split-K 8 x 2048. No atomics (deterministic).
__global__ __launch_bounds__(256) void gw_gemm_kernel(
    const float* __restrict__ Ak, const float* __restrict__ A0,  // [NB,NH]
    const float* __restrict__ Vk, const float* __restrict__ V0,  // [NB,NV]
    float* __restrict__ part)                                    // [8,NH,NV]
{
    __shared__ float Aks[16][68], A0s[16][68], Vks[16][68], V0s[16][68];
    int h0 = blockIdx.x * 64;
    int v0 = blockIdx.y * 64;
    int ks = blockIdx.z;
    int b0 = ks * (NB / 8);
    int tid = threadIdx.x;
    int r = tid >> 4;            // 0..15
    int c4 = (tid & 15) << 2;    // 0..60
    int tx = tid & 15, ty = tid >> 4;
    float acc[4][4];
#pragma unroll
    for (int i = 0; i < 4; i++)
#pragma unroll
        for (int j = 0; j < 4; j++) acc[i][j] = 0.0f;

    for (int bb = 0; bb < NB/8; bb += 16) {
        int b = b0 + bb + r;
        *(float4*)&Aks[r][c4] = *(const float4*)(Ak + (size_t)b*NH + h0 + c4);
        *(float4*)&A0s[r][c4] = *(const float4*)(A0 + (size_t)b*NH + h0 + c4);
        *(float4*)&Vks[r][c4] = *(const float4*)(Vk + (size_t)b*NV + v0 + c4);
        *(float4*)&V0s[r][c4] = *(const float4*)(V0 + (size_t)b*NV + v0 + c4);
        __syncthreads();
#pragma unroll
        for (int kk = 0; kk < 16; kk++) {
            float am[4], a0m[4], bn[4], b0n[4];
#pragma unroll
            for (int i = 0; i < 4; i++) { am[i] = Aks[kk][ty*4+i]; a0m[i] = A0s[kk][ty*4+i]; }
#pragma unroll
            for (int j = 0; j < 4; j++) { bn[j] = Vks[kk][tx*4+j]; b0n[j] = V0s[kk][tx*4+j]; }
#pragma unroll
            for (int i = 0; i < 4; i++)
#pragma unroll
                for (int j = 0; j < 4; j++) {
                    acc[i][j] = fmaf(am[i],  bn[j],  acc[i][j]);
                    acc[i][j] = fmaf(-a0m[i], b0n[j], acc[i][j]);
                }
        }
        __syncthreads();
    }
#pragma unroll
    for (int i = 0; i < 4; i++)
#pragma unroll
        for (int j = 0; j < 4; j++)
            part[(size_t)ks*GW_ELEMS + (size_t)(h0+ty*4+i)*NV + v0 + tx*4 + j] = acc[i][j];
}

// ---------------- g_vb partials: part[gy][v] = sum_{b chunk} invn*(vk-v0) ----------------
__global__ __launch_bounds__(256) void vb_part_kernel(
    const float* __restrict__ vk, const float* __restrict__ v0,
    const float* __restrict__ invn, float* __restrict__ part)
{
    int v = blockIdx.x * 256 + threadIdx.x;
    int b0 = blockIdx.y * (NB / 32);
    float s = 0.0f;
    for (int b = b0; b < b0 + NB/32; b++)
        s = fmaf(invn[b], vk[(size_t)b*NV + v] - v0[(size_t)b*NV + v], s);
    part[blockIdx.y * NV + v] = s;
}

// ---------------- g_hb partials: part[gx][h] = sum_{b chunk} (a_k - a_0) ----------------
__global__ __launch_bounds__(256) void hb_part_kernel(
    const float* __restrict__ ak, const float* __restrict__ a0,
    float* __restrict__ part)
{
    int h = threadIdx.x;
    int b0 = blockIdx.x * (NB / 32);
    float s = 0.0f;
    for (int b = b0; b < b0 + NB/32; b++)
        s += ak[(size_t)b*NH + h] - a0[(size_t)b*NH + h];
    part[blockIdx.x * NH + h] = s;
}

// ---------------- finalize: deterministic partial reductions into out ----------------
__global__ __launch_bounds__(256) void finalize_kernel(
    const float* __restrict__ gw_part, const float* __restrict__ vb_part,
    const float* __restrict__ hb_part, float* __restrict__ out)
{
    int i = blockIdx.x * 256 + threadIdx.x;
    if (i < GW_ELEMS) {
        float s = 0.0f;
#pragma unroll
        for (int k = 0; k < 8; k++) s += gw_part[(size_t)k*GW_ELEMS + i];
        out[i] = s;
    } else if (i < OUT_HB_OFF) {
        int v = i - OUT_VB_OFF;
        float s = 0.0f;
#pragma unroll
        for (int k = 0; k < 32; k++) s += vb_part[k*NV + v];
        out[i] = s;
    } else if (i < OUT_TOTAL) {
        int h = i - OUT_HB_OFF;
        float s = 0.0f;
#pragma unroll
        for (int k = 0; k < 32; k++) s += hb_part[k*NH + h];
        out[i] = s;
    }
}

// ---------------- launch ----------------
extern "C" void kernel_launch(void* const* d_in, const int* in_sizes, int n_in,
                              void* d_out, int out_size)
{
    (void)in_sizes; (void)n_in; (void)out_size;
    const float* batch = (const float*)d_in[0];
    const float* W     = (const float*)d_in[1];
    const float* vb    = (const float*)d_in[2];
    const float* hb    = (const float*)d_in[3];
    float* out = (float*)d_out;

    float *pv, *ph, *pprev, *ppreh, *ppreh0, *pinvn, *pgw, *pvbp, *phbp;
    cudaGetSymbolAddress((void**)&pv,     g_v);
    cudaGetSymbolAddress((void**)&ph,     g_h);
    cudaGetSymbolAddress((void**)&pprev,  g_prev);
    cudaGetSymbolAddress((void**)&ppreh,  g_preh);
    cudaGetSymbolAddress((void**)&ppreh0, g_preh0);
    cudaGetSymbolAddress((void**)&pinvn,  g_invn);
    cudaGetSymbolAddress((void**)&pgw,    g_gw_part);
    cudaGetSymbolAddress((void**)&pvbp,   g_vb_part);
    cudaGetSymbolAddress((void**)&phbp,   g_hb_part);

    // JAX partitionable split: keys = split(key(42), 16).reshape(8, 2)
    // key_m = (o0, o1) = threefry2x32(parent=(0,42), c0 = m>>32 = 0, c1 = m)
    uint32_t keys[16][2];
    for (int m = 0; m < 16; m++) {
        uint32_t o0, o1;
        threefry2x32(0u, 42u, 0u, (uint32_t)m, o0, o1);
        keys[m][0] = o0; keys[m][1] = o1;
    }

    cudaMemcpyAsync(pv, batch, sizeof(float)*(size_t)NB*NV, cudaMemcpyDeviceToDevice, 0);

    dim3 ggrid(NB/128, NH/64);
    const int totH = NB*NH;   // 4194304
    const int totV = NB*NV;   // 16777216

    for (int s = 0; s < KSTEPS; s++) {
        gemm_nt_kernel<<<ggrid, 256>>>(pv, W, hb, ppreh);
        sample_kernel<<<totH/512, 256>>>(ppreh, ph, keys[2*s][0], keys[2*s][1], totH);
        spmm_hW_kernel<<<NB/8, 256>>>(ph, W, vb, pprev);
        sample_kernel<<<totV/512, 256>>>(pprev, pv, keys[2*s+1][0], keys[2*s+1][1], totV);
    }

    gemm_nt_kernel<<<ggrid, 256>>>(pv, W, hb, ppreh);      // pre_k
    gemm_nt_kernel<<<ggrid, 256>>>(batch, W, hb, ppreh0);  // pre for ph0
    invn_kernel<<<NB/8, 256>>>(ppreh, pv, vb, pinvn);
    atrans_kernel<<<NB*NH/256, 256>>>(ppreh,  pinvn);      // a_k = invn*phk
    atrans_kernel<<<NB*NH/256, 256>>>(ppreh0, pinvn);      // a_0 = invn*ph0
    gw_gemm_kernel<<<dim3(NH/64, NV/64, 8), 256>>>(ppreh, ppreh0, pv, batch, pgw);
    vb_part_kernel<<<dim3(NV/256, 32), 256>>>(pv, batch, pinvn, pvbp);
    hb_part_kernel<<<32, 256>>>(ppreh, ppreh0, phbp);
    finalize_kernel<<<(OUT_TOTAL + 255)/256, 256>>>(pgw, pvbp, phbp, out);
}

// round 6
// speedup vs baseline: 1.9819x; 1.9819x over previous
#include <cuda_runtime.h>
#include <cuda_bf16.h>
#include <cstdint>
#include <cstddef>

#define NB 16384
#define NV 1024
#define NH 256
#define KSTEPS 8
#define GW_ELEMS (NH*NV)          // 262144
#define OUT_VB_OFF GW_ELEMS
#define OUT_HB_OFF (GW_ELEMS+NV)
#define OUT_TOTAL (GW_ELEMS+NV+NH)
#define GW_SPLITK 16

typedef __nv_bfloat16 bf16;

// ---------------- static scratch ----------------
__device__ float g_v[NB*NV];
__device__ bf16  g_vbf[NB*NV];
__device__ bf16  g_batchbf[NB*NV];
__device__ float g_h[NB*NH];
__device__ float g_prev[NB*NV];
__device__ float g_preh[NB*NH];     // pre_k -> a_k
__device__ float g_preh0[NB*NH];    // pre0 -> a_0
__device__ float g_invn[NB];
__device__ bf16  g_whi[NH*NV];
__device__ bf16  g_wlo[NH*NV];
__device__ bf16  g_akT_hi[NH*NB];
__device__ bf16  g_akT_lo[NH*NB];
__device__ bf16  g_na0T_hi[NH*NB];
__device__ bf16  g_na0T_lo[NH*NB];
__device__ bf16  g_vkT[NV*NB];
__device__ bf16  g_v0T[NV*NB];
__device__ float g_gw_part[GW_SPLITK*GW_ELEMS];
__device__ float g_vb_part[32*NV];
__device__ float g_hb_part[32*NH];

// ---------------- threefry2x32 (JAX partitionable) ----------------
__host__ __device__ __forceinline__ void threefry2x32(
    uint32_t k0, uint32_t k1, uint32_t c0, uint32_t c1,
    uint32_t& o0, uint32_t& o1)
{
    uint32_t k2 = k0 ^ k1 ^ 0x1BD11BDAu;
    uint32_t x0 = c0 + k0, x1 = c1 + k1;
#define TF_R(r) { x0 += x1; x1 = (x1 << (r)) | (x1 >> (32 - (r))); x1 ^= x0; }
    TF_R(13) TF_R(15) TF_R(26) TF_R(6)
    x0 += k1; x1 += k2 + 1u;
    TF_R(17) TF_R(29) TF_R(16) TF_R(24)
    x0 += k2; x1 += k0 + 2u;
    TF_R(13) TF_R(15) TF_R(26) TF_R(6)
    x0 += k0; x1 += k1 + 3u;
    TF_R(17) TF_R(29) TF_R(16) TF_R(24)
    x0 += k1; x1 += k2 + 4u;
    TF_R(13) TF_R(15) TF_R(26) TF_R(6)
    x0 += k2; x1 += k0 + 5u;
#undef TF_R
    o0 = x0; o1 = x1;
}

__device__ __forceinline__ float tf_uniform(uint32_t bits) {
    return __uint_as_float((bits >> 9) | 0x3f800000u) - 1.0f;
}
__device__ __forceinline__ float sigmoid_f(float x) {
    return 1.0f / (1.0f + expf(-x));
}

// ---------------- cp.async helpers ----------------
__device__ __forceinline__ void cpa16(void* s, const void* g) {
    uint32_t sa = (uint32_t)__cvta_generic_to_shared(s);
    asm volatile("cp.async.ca.shared.global [%0], [%1], 16;\n" :: "r"(sa), "l"(g));
}
__device__ __forceinline__ void cpa_commit() {
    asm volatile("cp.async.commit_group;\n" ::);
}
__device__ __forceinline__ void cpa_wait1() {
    asm volatile("cp.async.wait_group 1;\n" ::);
}
__device__ __forceinline__ void cpa_wait0() {
    asm volatile("cp.async.wait_group 0;\n" ::);
}

__device__ __forceinline__ void mma16816(float* c, const uint32_t* a, const uint32_t* b) {
    asm volatile(
        "mma.sync.aligned.m16n8k16.row.col.f32.bf16.bf16.f32 "
        "{%0,%1,%2,%3}, {%4,%5,%6,%7}, {%8,%9}, {%0,%1,%2,%3};\n"
        : "+f"(c[0]), "+f"(c[1]), "+f"(c[2]), "+f"(c[3])
        : "r"(a[0]), "r"(a[1]), "r"(a[2]), "r"(a[3]), "r"(b[0]), "r"(b[1]));
}

// SMEM tile: 128 rows x 32 bf16, row stride 40 bf16 (80B, 16B-aligned, conflict-free)
#define TSTRIDE 40

// load one 128x32 bf16 tile: 512 16B-chunks, 256 threads x 2
__device__ __forceinline__ void load_tile(bf16* s, const bf16* g, size_t ldg, int tid) {
#pragma unroll
    for (int i = 0; i < 2; i++) {
        int c = tid + 256*i;
        int row = c >> 2, w = c & 3;
        cpa16(s + row*TSTRIDE + w*8, g + (size_t)row*ldg + w*8);
    }
}

// compute one BK=32 tile: warp (wm 0..1, wn 0..3), acc[4][4][4]
__device__ __forceinline__ void mma_tile(const bf16* sA, const bf16* sB,
                                         int wm, int wn, int lane, float acc[4][4][4]) {
#pragma unroll
    for (int kk = 0; kk < 32; kk += 16) {
        uint32_t a[4][4], b[4][2];
#pragma unroll
        for (int mi = 0; mi < 4; mi++) {
            const bf16* p = sA + (wm*64 + mi*16 + (lane>>2))*TSTRIDE + kk + 2*(lane&3);
            a[mi][0] = *(const uint32_t*)p;
            a[mi][1] = *(const uint32_t*)(p + 8*TSTRIDE);
            a[mi][2] = *(const uint32_t*)(p + 8);
            a[mi][3] = *(const uint32_t*)(p + 8*TSTRIDE + 8);
        }
#pragma unroll
        for (int ni = 0; ni < 4; ni++) {
            const bf16* p = sB + (wn*32 + ni*8 + (lane>>2))*TSTRIDE + kk + 2*(lane&3);
            b[ni][0] = *(const uint32_t*)p;
            b[ni][1] = *(const uint32_t*)(p + 8);
        }
#pragma unroll
        for (int mi = 0; mi < 4; mi++)
#pragma unroll
            for (int ni = 0; ni < 4; ni++)
                mma16816(acc[mi][ni], a[mi], b[ni]);
    }
}

// ---------------- forward GEMM: pre[M,NH] = v[M,NV] @ (Whi|Wlo)^T + hb ----------------
// BM=128, BN=128, BK=32, 64 iters (2 passes over K=1024). grid (128, 2), 256 thr.
__global__ __launch_bounds__(256) void fgemm_kernel(
    const bf16* __restrict__ A, const bf16* __restrict__ Whi,
    const bf16* __restrict__ Wlo, const float* __restrict__ bias,
    float* __restrict__ C)
{
    __shared__ __align__(16) bf16 sA[2][128*TSTRIDE];
    __shared__ __align__(16) bf16 sB[2][128*TSTRIDE];
    int m0 = blockIdx.x * 128;
    int n0 = blockIdx.y * 128;
    int tid = threadIdx.x;
    int warp = tid >> 5, lane = tid & 31;
    int wm = warp & 1, wn = warp >> 1;

    float acc[4][4][4];
#pragma unroll
    for (int mi = 0; mi < 4; mi++)
#pragma unroll
        for (int ni = 0; ni < 4; ni++)
#pragma unroll
            for (int j = 0; j < 4; j++) acc[mi][ni][j] = 0.0f;

    const int NIT = 64;
    // prefetch tile 0
    load_tile(sA[0], A + (size_t)m0*NV, NV, tid);
    load_tile(sB[0], Whi + (size_t)n0*NV, NV, tid);
    cpa_commit();

    for (int it = 0; it < NIT; it++) {
        int cur = it & 1;
        if (it + 1 < NIT) {
            int jt = it + 1;
            int k = (jt & 31) * 32;
            const bf16* Bp = (jt < 32) ? Whi : Wlo;
            load_tile(sA[cur^1], A + (size_t)m0*NV + k, NV, tid);
            load_tile(sB[cur^1], Bp + (size_t)n0*NV + k, NV, tid);
            cpa_commit();
            cpa_wait1();
        } else {
            cpa_wait0();
        }
        __syncthreads();
        mma_tile(sA[cur], sB[cur], wm, wn, lane, acc);
        __syncthreads();
    }

#pragma unroll
    for (int mi = 0; mi < 4; mi++) {
        int m = m0 + wm*64 + mi*16 + (lane>>2);
#pragma unroll
        for (int ni = 0; ni < 4; ni++) {
            int n = n0 + wn*32 + ni*8 + 2*(lane&3);
            float2 b2 = *(const float2*)&bias[n];
            float2 r0 = { acc[mi][ni][0] + b2.x, acc[mi][ni][1] + b2.y };
            float2 r1 = { acc[mi][ni][2] + b2.x, acc[mi][ni][3] + b2.y };
            *(float2*)&C[(size_t)m*NH + n] = r0;
            *(float2*)&C[(size_t)(m+8)*NH + n] = r1;
        }
    }
}

// ---------------- gw GEMM: part[ks][h][v] = sum over 4 passes of A_p^T-style NT mma ----
// A arrays [NH,NB] bf16 (akhi, aklo, -a0hi, -a0lo), B arrays [NV,NB] (vkT, v0T)
// BM=128 (M=256), BN=128 (N=1024), splitK=16 (chunk 1024), 4 passes -> 128 iters
__global__ __launch_bounds__(256) void gw_mma_kernel(
    const bf16* __restrict__ A0p, const bf16* __restrict__ A1p,
    const bf16* __restrict__ A2p, const bf16* __restrict__ A3p,
    const bf16* __restrict__ Bk, const bf16* __restrict__ B0,
    float* __restrict__ part)
{
    __shared__ __align__(16) bf16 sA[2][128*TSTRIDE];
    __shared__ __align__(16) bf16 sB[2][128*TSTRIDE];
    int m0 = blockIdx.x * 128;
    int n0 = blockIdx.y * 128;
    int ks = blockIdx.z;
    size_t kbase = (size_t)ks * (NB / GW_SPLITK);
    int tid = threadIdx.x;
    int warp = tid >> 5, lane = tid & 31;
    int wm = warp & 1, wn = warp >> 1;

    const bf16* Ap[4] = { A0p, A1p, A2p, A3p };
    const bf16* Bp[4] = { Bk, Bk, B0, B0 };

    float acc[4][4][4];
#pragma unroll
    for (int mi = 0; mi < 4; mi++)
#pragma unroll
        for (int ni = 0; ni < 4; ni++)
#pragma unroll
            for (int j = 0; j < 4; j++) acc[mi][ni][j] = 0.0f;

    const int NIT = 128;
    load_tile(sA[0], Ap[0] + (size_t)m0*NB + kbase, NB, tid);
    load_tile(sB[0], Bp[0] + (size_t)n0*NB + kbase, NB, tid);
    cpa_commit();

    for (int it = 0; it < NIT; it++) {
        int cur = it & 1;
        if (it + 1 < NIT) {
            int jt = it + 1;
            int p = jt >> 5;
            size_t k = kbase + (size_t)(jt & 31) * 32;
            load_tile(sA[cur^1], Ap[p] + (size_t)m0*NB + k, NB, tid);
            load_tile(sB[cur^1], Bp[p] + (size_t)n0*NB + k, NB, tid);
            cpa_commit();
            cpa_wait1();
        } else {
            cpa_wait0();
        }
        __syncthreads();
        mma_tile(sA[cur], sB[cur], wm, wn, lane, acc);
        __syncthreads();
    }

#pragma unroll
    for (int mi = 0; mi < 4; mi++) {
        int m = m0 + wm*64 + mi*16 + (lane>>2);
#pragma unroll
        for (int ni = 0; ni < 4; ni++) {
            int n = n0 + wn*32 + ni*8 + 2*(lane&3);
            float2 r0 = { acc[mi][ni][0], acc[mi][ni][1] };
            float2 r1 = { acc[mi][ni][2], acc[mi][ni][3] };
            *(float2*)&part[(size_t)ks*GW_ELEMS + (size_t)m*NV + n] = r0;
            *(float2*)&part[(size_t)ks*GW_ELEMS + (size_t)(m+8)*NV + n] = r1;
        }
    }
}

// ---------------- sampler (partitionable threefry, fold=xor) ----------------
__global__ __launch_bounds__(256) void sample_kernel(
    const float* __restrict__ pre, float* __restrict__ out,
    bf16* __restrict__ outbf, uint32_t k0, uint32_t k1, int total)
{
    int e = (blockIdx.x * blockDim.x + threadIdx.x) * 2;
    if (e >= total) return;
    uint32_t a0, a1, b0, b1;
    threefry2x32(k0, k1, 0u, (uint32_t)e,       a0, a1);
    threefry2x32(k0, k1, 0u, (uint32_t)(e + 1), b0, b1);
    float u0 = tf_uniform(a0 ^ a1);
    float u1 = tf_uniform(b0 ^ b1);
    float v0 = (u0 < sigmoid_f(pre[e]))     ? 1.0f : 0.0f;
    float v1 = (u1 < sigmoid_f(pre[e + 1])) ? 1.0f : 0.0f;
    out[e] = v0; out[e+1] = v1;
    if (outbf) {
        outbf[e]   = __float2bfloat16(v0);
        outbf[e+1] = __float2bfloat16(v1);
    }
}

// ---------------- sparse h @ W + vb ----------------
__global__ __launch_bounds__(256) void spmm_hW_kernel(
    const float* __restrict__ h, const float* __restrict__ Wm,
    const float* __restrict__ vb, float* __restrict__ prev)
{
    int warp = (blockIdx.x * blockDim.x + threadIdx.x) >> 5;
    int lane = threadIdx.x & 31;
    if (warp >= NB) return;
    const float* hr = h + (size_t)warp * NH;
    float acc[32];
#pragma unroll
    for (int t = 0; t < 32; t++) acc[t] = vb[t*32 + lane];
#pragma unroll
    for (int g = 0; g < 8; g++) {
        float hv = hr[g*32 + lane];
        unsigned mask = __ballot_sync(0xffffffffu, hv != 0.0f);
        while (mask) {
            int bit = __ffs(mask) - 1; mask &= mask - 1;
            const float* wr = Wm + (size_t)(g*32 + bit) * NV;
#pragma unroll
            for (int t = 0; t < 32; t++) acc[t] += wr[t*32 + lane];
        }
    }
    float* outp = prev + (size_t)warp * NV;
#pragma unroll
    for (int t = 0; t < 32; t++) outp[t*32 + lane] = acc[t];
}

// ---------------- inv_norm ----------------
__global__ __launch_bounds__(256) void invn_kernel(
    const float* __restrict__ prek, const float* __restrict__ vk,
    const float* __restrict__ vb, float* __restrict__ invn)
{
    int warp = (blockIdx.x * blockDim.x + threadIdx.x) >> 5;
    int lane = threadIdx.x & 31;
    if (warp >= NB) return;
    float s = 0.0f;
    const float* pr = prek + (size_t)warp * NH;
#pragma unroll
    for (int t = 0; t < 8; t++) {
        float x = pr[t*32 + lane];
        s += fmaxf(x, 0.0f) + log1pf(expf(-fabsf(x)));
    }
    const float* vr = vk + (size_t)warp * NV;
#pragma unroll
    for (int t = 0; t < 32; t++) s = fmaf(vr[t*32 + lane], vb[t*32 + lane], s);
#pragma unroll
    for (int o = 16; o > 0; o >>= 1) s += __shfl_xor_sync(0xffffffffu, s, o);
    if (lane == 0) invn[warp] = expf(-s) * (1.0f / (float)NB);
}

// ---------------- a = invn[b] * sigmoid(pre), in place ----------------
__global__ __launch_bounds__(256) void atrans_kernel(
    float* __restrict__ a, const float* __restrict__ invn)
{
    int i = blockIdx.x * blockDim.x + threadIdx.x;
    if (i >= NB * NH) return;
    int b = i >> 8;
    a[i] = invn[b] * sigmoid_f(a[i]);
}

// ---------------- transpose + bf16 hi/lo split for a-matrices ----------------
// src [NB,NH] f32 -> dhi/dlo [NH,NB] bf16 (optionally negated)
__global__ __launch_bounds__(256) void trans_a_kernel(
    const float* __restrict__ src, float sign,
    bf16* __restrict__ dhi, bf16* __restrict__ dlo)
{
    __shared__ float t[32][33];
    int b0 = blockIdx.x * 32, h0 = blockIdx.y * 32;
    int tid = threadIdx.x;
#pragma unroll
    for (int i = 0; i < 4; i++) {
        int idx = tid + 256*i; int bl = idx >> 5, hl = idx & 31;
        t[hl][bl] = src[(size_t)(b0+bl)*NH + h0 + hl];
    }
    __syncthreads();
#pragma unroll
    for (int i = 0; i < 4; i++) {
        int idx = tid + 256*i; int hl = idx >> 5, bl = idx & 31;
        float v = sign * t[hl][bl];
        bf16 hi = __float2bfloat16(v);
        float lo = v - __bfloat162float(hi);
        size_t o = (size_t)(h0+hl)*NB + b0 + bl;
        dhi[o] = hi; dlo[o] = __float2bfloat16(lo);
    }
}

// src [NB,NV] f32 (binary) -> dst [NV,NB] bf16
__global__ __launch_bounds__(256) void trans_v_kernel(
    const float* __restrict__ src, bf16* __restrict__ dst)
{
    __shared__ float t[32][33];
    int b0 = blockIdx.x * 32, v0 = blockIdx.y * 32;
    int tid = threadIdx.x;
#pragma unroll
    for (int i = 0; i < 4; i++) {
        int idx = tid + 256*i; int bl = idx >> 5, vl = idx & 31;
        t[vl][bl] = src[(size_t)(b0+bl)*NV + v0 + vl];
    }
    __syncthreads();
#pragma unroll
    for (int i = 0; i < 4; i++) {
        int idx = tid + 256*i; int vl = idx >> 5, bl = idx & 31;
        dst[(size_t)(v0+vl)*NB + b0 + bl] = __float2bfloat16(t[vl][bl]);
    }
}

// ---------------- W split, batch convert ----------------
__global__ __launch_bounds__(256) void wsplit_kernel(
    const float* __restrict__ W, bf16* __restrict__ whi, bf16* __restrict__ wlo)
{
    int i = blockIdx.x * 256 + threadIdx.x;
    if (i >= NH*NV) return;
    float w = W[i];
    bf16 hi = __float2bfloat16(w);
    whi[i] = hi;
    wlo[i] = __float2bfloat16(w - __bfloat162float(hi));
}

__global__ __launch_bounds__(256) void bconv_kernel(
    const float* __restrict__ src, bf16* __restrict__ dst, int n)
{
    int i = blockIdx.x * 256 + threadIdx.x;
    if (i < n) dst[i] = __float2bfloat16(src[i]);
}

// ---------------- g_vb / g_hb partials ----------------
__global__ __launch_bounds__(256) void vb_part_kernel(
    const float* __restrict__ vk, const float* __restrict__ v0,
    const float* __restrict__ invn, float* __restrict__ part)
{
    int v = blockIdx.x * 256 + threadIdx.x;
    int b0 = blockIdx.y * (NB / 32);
    float s = 0.0f;
    for (int b = b0; b < b0 + NB/32; b++)
        s = fmaf(invn[b], vk[(size_t)b*NV + v] - v0[(size_t)b*NV + v], s);
    part[blockIdx.y * NV + v] = s;
}

__global__ __launch_bounds__(256) void hb_part_kernel(
    const float* __restrict__ ak, const float* __restrict__ a0,
    float* __restrict__ part)
{
    int h = threadIdx.x;
    int b0 = blockIdx.x * (NB / 32);
    float s = 0.0f;
    for (int b = b0; b < b0 + NB/32; b++)
        s += ak[(size_t)b*NH + h] - a0[(size_t)b*NH + h];
    part[blockIdx.x * NH + h] = s;
}

// ---------------- finalize ----------------
__global__ __launch_bounds__(256) void finalize_kernel(
    const float* __restrict__ gw_part, const float* __restrict__ vb_part,
    const float* __restrict__ hb_part, float* __restrict__ out)
{
    int i = blockIdx.x * 256 + threadIdx.x;
    if (i < GW_ELEMS) {
        float s = 0.0f;
#pragma unroll
        for (int k = 0; k < GW_SPLITK; k++) s += gw_part[(size_t)k*GW_ELEMS + i];
        out[i] = s;
    } else if (i < OUT_HB_OFF) {
        int v = i - OUT_VB_OFF;
        float s = 0.0f;
#pragma unroll
        for (int k = 0; k < 32; k++) s += vb_part[k*NV + v];
        out[i] = s;
    } else if (i < OUT_TOTAL) {
        int h = i - OUT_HB_OFF;
        float s = 0.0f;
#pragma unroll
        for (int k = 0; k < 32; k++) s += hb_part[k*NH + h];
        out[i] = s;
    }
}

// ---------------- launch ----------------
extern "C" void kernel_launch(void* const* d_in, const int* in_sizes, int n_in,
                              void* d_out, int out_size)
{
    (void)in_sizes; (void)n_in; (void)out_size;
    const float* batch = (const float*)d_in[0];
    const float* W     = (const float*)d_in[1];
    const float* vb    = (const float*)d_in[2];
    const float* hb    = (const float*)d_in[3];
    float* out = (float*)d_out;

    float *pv, *ph, *pprev, *ppreh, *ppreh0, *pinvn, *pgw, *pvbp, *phbp;
    bf16 *pvbf, *pbbf, *pwhi, *pwlo, *pakhi, *paklo, *pna0hi, *pna0lo, *pvkT, *pv0T;
    cudaGetSymbolAddress((void**)&pv,     g_v);
    cudaGetSymbolAddress((void**)&pvbf,   g_vbf);
    cudaGetSymbolAddress((void**)&pbbf,   g_batchbf);
    cudaGetSymbolAddress((void**)&ph,     g_h);
    cudaGetSymbolAddress((void**)&pprev,  g_prev);
    cudaGetSymbolAddress((void**)&ppreh,  g_preh);
    cudaGetSymbolAddress((void**)&ppreh0, g_preh0);
    cudaGetSymbolAddress((void**)&pinvn,  g_invn);
    cudaGetSymbolAddress((void**)&pwhi,   g_whi);
    cudaGetSymbolAddress((void**)&pwlo,   g_wlo);
    cudaGetSymbolAddress((void**)&pakhi,  g_akT_hi);
    cudaGetSymbolAddress((void**)&paklo,  g_akT_lo);
    cudaGetSymbolAddress((void**)&pna0hi, g_na0T_hi);
    cudaGetSymbolAddress((void**)&pna0lo, g_na0T_lo);
    cudaGetSymbolAddress((void**)&pvkT,   g_vkT);
    cudaGetSymbolAddress((void**)&pv0T,   g_v0T);
    cudaGetSymbolAddress((void**)&pgw,    g_gw_part);
    cudaGetSymbolAddress((void**)&pvbp,   g_vb_part);
    cudaGetSymbolAddress((void**)&phbp,   g_hb_part);

    // JAX partitionable split: key_m = threefry2x32((0,42), 0, m)
    uint32_t keys[16][2];
    for (int m = 0; m < 16; m++) {
        uint32_t o0, o1;
        threefry2x32(0u, 42u, 0u, (uint32_t)m, o0, o1);
        keys[m][0] = o0; keys[m][1] = o1;
    }

    const int totH = NB*NH, totV = NB*NV;
    dim3 fgrid(NB/128, NH/128);   // (128, 2)

    wsplit_kernel<<<(NH*NV + 255)/256, 256>>>(W, pwhi, pwlo);
    bconv_kernel<<<(totV + 255)/256, 256>>>(batch, pbbf, totV);

    for (int s = 0; s < KSTEPS; s++) {
        const bf16* Ain = (s == 0) ? pbbf : pvbf;
        fgemm_kernel<<<fgrid, 256>>>(Ain, pwhi, pwlo, hb, ppreh);
        sample_kernel<<<totH/512, 256>>>(ppreh, ph, (bf16*)nullptr,
                                         keys[2*s][0], keys[2*s][1], totH);
        spmm_hW_kernel<<<NB/8, 256>>>(ph, W, vb, pprev);
        sample_kernel<<<totV/512, 256>>>(pprev, pv, pvbf,
                                         keys[2*s+1][0], keys[2*s+1][1], totV);
    }

    fgemm_kernel<<<fgrid, 256>>>(pvbf, pwhi, pwlo, hb, ppreh);    // pre_k
    fgemm_kernel<<<fgrid, 256>>>(pbbf, pwhi, pwlo, hb, ppreh0);   // pre for ph0
    invn_kernel<<<NB/8, 256>>>(ppreh, pv, vb, pinvn);
    atrans_kernel<<<totH/256, 256>>>(ppreh,  pinvn);   // a_k
    atrans_kernel<<<totH/256, 256>>>(ppreh0, pinvn);   // a_0

    trans_a_kernel<<<dim3(NB/32, NH/32), 256>>>(ppreh,  1.0f, pakhi, paklo);
    trans_a_kernel<<<dim3(NB/32, NH/32), 256>>>(ppreh0, -1.0f, pna0hi, pna0lo);
    trans_v_kernel<<<dim3(NB/32, NV/32), 256>>>(pv, pvkT);
    trans_v_kernel<<<dim3(NB/32, NV/32), 256>>>(batch, pv0T);

    gw_mma_kernel<<<dim3(NH/128, NV/128, GW_SPLITK), 256>>>(
        pakhi, paklo, pna0hi, pna0lo, pvkT, pv0T, pgw);

    vb_part_kernel<<<dim3(NV/256, 32), 256>>>(pv, batch, pinvn, pvbp);
    hb_part_kernel<<<32, 256>>>(ppreh, ppreh0, phbp);
    finalize_kernel<<<(OUT_TOTAL + 255)/256, 256>>>(pgw, pvbp, phbp, out);
}

// round 9
// speedup vs baseline: 2.0818x; 1.0504x over previous
#include <cuda_runtime.h>
#include <cuda_bf16.h>
#include <cstdint>
#include <cstddef>

#define NB 16384
#define NV 1024
#define NH 256
#define KSTEPS 8
#define GW_ELEMS (NH*NV)          // 262144
#define OUT_VB_OFF GW_ELEMS
#define OUT_HB_OFF (GW_ELEMS+NV)
#define OUT_TOTAL (GW_ELEMS+NV+NH)
#define GW_SPLITK 16

typedef __nv_bfloat16 bf16;

// ---------------- static scratch ----------------
__device__ bf16  g_vbf[NB*NV];      // current visible state, bf16 (binary, exact)
__device__ bf16  g_batchbf[NB*NV];
__device__ bf16  g_hbf[NB*NH];      // hidden state, bf16 (binary, exact)
__device__ float g_preh[NB*NH];     // pre_k -> a_k
__device__ float g_preh0[NB*NH];    // pre0 -> a_0
__device__ float g_invn[NB];
__device__ bf16  g_whi[NH*NV];
__device__ bf16  g_wlo[NH*NV];
__device__ bf16  g_akT_hi[NH*NB];
__device__ bf16  g_akT_lo[NH*NB];
__device__ bf16  g_na0T_hi[NH*NB];
__device__ bf16  g_na0T_lo[NH*NB];
__device__ bf16  g_vkT[NV*NB];
__device__ bf16  g_v0T[NV*NB];
__device__ float g_gw_part[GW_SPLITK*GW_ELEMS];
__device__ float g_vb_part[32*NV];
__device__ float g_hb_part[32*NH];

// ---------------- threefry2x32 (JAX partitionable) ----------------
__host__ __device__ __forceinline__ void threefry2x32(
    uint32_t k0, uint32_t k1, uint32_t c0, uint32_t c1,
    uint32_t& o0, uint32_t& o1)
{
    uint32_t k2 = k0 ^ k1 ^ 0x1BD11BDAu;
    uint32_t x0 = c0 + k0, x1 = c1 + k1;
#define TF_R(r) { x0 += x1; x1 = (x1 << (r)) | (x1 >> (32 - (r))); x1 ^= x0; }
    TF_R(13) TF_R(15) TF_R(26) TF_R(6)
    x0 += k1; x1 += k2 + 1u;
    TF_R(17) TF_R(29) TF_R(16) TF_R(24)
    x0 += k2; x1 += k0 + 2u;
    TF_R(13) TF_R(15) TF_R(26) TF_R(6)
    x0 += k0; x1 += k1 + 3u;
    TF_R(17) TF_R(29) TF_R(16) TF_R(24)
    x0 += k1; x1 += k2 + 4u;
    TF_R(13) TF_R(15) TF_R(26) TF_R(6)
    x0 += k2; x1 += k0 + 5u;
#undef TF_R
    o0 = x0; o1 = x1;
}

__device__ __forceinline__ float tf_uniform(uint32_t bits) {
    return __uint_as_float((bits >> 9) | 0x3f800000u) - 1.0f;
}
__device__ __forceinline__ float sigmoid_f(float x) {
    return 1.0f / (1.0f + expf(-x));
}
// one partitionable-threefry binary sample: (u < sigmoid(pre)) ? 1 : 0
__device__ __forceinline__ float tf_sample(uint32_t k0, uint32_t k1, uint32_t e, float pre) {
    uint32_t o0, o1;
    threefry2x32(k0, k1, 0u, e, o0, o1);
    return (tf_uniform(o0 ^ o1) < sigmoid_f(pre)) ? 1.0f : 0.0f;
}

// ---------------- cp.async helpers ----------------
__device__ __forceinline__ void cpa16(void* s, const void* g) {
    uint32_t sa = (uint32_t)__cvta_generic_to_shared(s);
    asm volatile("cp.async.ca.shared.global [%0], [%1], 16;\n" :: "r"(sa), "l"(g));
}
__device__ __forceinline__ void cpa_commit() {
    asm volatile("cp.async.commit_group;\n" ::);
}
__device__ __forceinline__ void cpa_wait1() {
    asm volatile("cp.async.wait_group 1;\n" ::);
}
__device__ __forceinline__ void cpa_wait0() {
    asm volatile("cp.async.wait_group 0;\n" ::);
}

__device__ __forceinline__ void mma16816(float* c, const uint32_t* a, const uint32_t* b) {
    asm volatile(
        "mma.sync.aligned.m16n8k16.row.col.f32.bf16.bf16.f32 "
        "{%0,%1,%2,%3}, {%4,%5,%6,%7}, {%8,%9}, {%0,%1,%2,%3};\n"
        : "+f"(c[0]), "+f"(c[1]), "+f"(c[2]), "+f"(c[3])
        : "r"(a[0]), "r"(a[1]), "r"(a[2]), "r"(a[3]), "r"(b[0]), "r"(b[1]));
}

// SMEM tile: 128 rows x 32 bf16, row stride 40 bf16 (80B, 16B-aligned, conflict-free)
#define TSTRIDE 40

__device__ __forceinline__ void load_tile(bf16* s, const bf16* g, size_t ldg, int tid) {
#pragma unroll
    for (int i = 0; i < 2; i++) {
        int c = tid + 256*i;
        int row = c >> 2, w = c & 3;
        cpa16(s + row*TSTRIDE + w*8, g + (size_t)row*ldg + w*8);
    }
}

__device__ __forceinline__ void mma_tile(const bf16* sA, const bf16* sB,
                                         int wm, int wn, int lane, float acc[4][4][4]) {
#pragma unroll
    for (int kk = 0; kk < 32; kk += 16) {
        uint32_t a[4][4], b[4][2];
#pragma unroll
        for (int mi = 0; mi < 4; mi++) {
            const bf16* p = sA + (wm*64 + mi*16 + (lane>>2))*TSTRIDE + kk + 2*(lane&3);
            a[mi][0] = *(const uint32_t*)p;
            a[mi][1] = *(const uint32_t*)(p + 8*TSTRIDE);
            a[mi][2] = *(const uint32_t*)(p + 8);
            a[mi][3] = *(const uint32_t*)(p + 8*TSTRIDE + 8);
        }
#pragma unroll
        for (int ni = 0; ni < 4; ni++) {
            const bf16* p = sB + (wn*32 + ni*8 + (lane>>2))*TSTRIDE + kk + 2*(lane&3);
            b[ni][0] = *(const uint32_t*)p;
            b[ni][1] = *(const uint32_t*)(p + 8);
        }
#pragma unroll
        for (int mi = 0; mi < 4; mi++)
#pragma unroll
            for (int ni = 0; ni < 4; ni++)
                mma16816(acc[mi][ni], a[mi], b[ni]);
    }
}

// ---------------- forward GEMM: pre[M,NH] = v[M,NV] @ (Whi|Wlo)^T + hb ----------------
// SAMPLE=true: fused hidden sampler writes bf16 h. SAMPLE=false: writes f32 pre.
template<bool SAMPLE>
__global__ __launch_bounds__(256) void fgemm_kernel(
    const bf16* __restrict__ A, const bf16* __restrict__ Whi,
    const bf16* __restrict__ Wlo, const float* __restrict__ bias,
    float* __restrict__ C, bf16* __restrict__ H,
    uint32_t k0, uint32_t k1)
{
    __shared__ __align__(16) bf16 sA[2][128*TSTRIDE];
    __shared__ __align__(16) bf16 sB[2][128*TSTRIDE];
    int m0 = blockIdx.x * 128;
    int n0 = blockIdx.y * 128;
    int tid = threadIdx.x;
    int warp = tid >> 5, lane = tid & 31;
    int wm = warp & 1, wn = warp >> 1;

    float acc[4][4][4];
#pragma unroll
    for (int mi = 0; mi < 4; mi++)
#pragma unroll
        for (int ni = 0; ni < 4; ni++)
#pragma unroll
            for (int j = 0; j < 4; j++) acc[mi][ni][j] = 0.0f;

    const int NIT = 64;
    load_tile(sA[0], A + (size_t)m0*NV, NV, tid);
    load_tile(sB[0], Whi + (size_t)n0*NV, NV, tid);
    cpa_commit();

    for (int it = 0; it < NIT; it++) {
        int cur = it & 1;
        if (it + 1 < NIT) {
            int jt = it + 1;
            int k = (jt & 31) * 32;
            const bf16* Bp = (jt < 32) ? Whi : Wlo;
            load_tile(sA[cur^1], A + (size_t)m0*NV + k, NV, tid);
            load_tile(sB[cur^1], Bp + (size_t)n0*NV + k, NV, tid);
            cpa_commit();
            cpa_wait1();
        } else {
            cpa_wait0();
        }
        __syncthreads();
        mma_tile(sA[cur], sB[cur], wm, wn, lane, acc);
        __syncthreads();
    }

#pragma unroll
    for (int mi = 0; mi < 4; mi++) {
        int m = m0 + wm*64 + mi*16 + (lane>>2);
#pragma unroll
        for (int ni = 0; ni < 4; ni++) {
            int n = n0 + wn*32 + ni*8 + 2*(lane&3);
            float2 b2 = *(const float2*)&bias[n];
            float p00 = acc[mi][ni][0] + b2.x;
            float p01 = acc[mi][ni][1] + b2.y;
            float p10 = acc[mi][ni][2] + b2.x;
            float p11 = acc[mi][ni][3] + b2.y;
            if (SAMPLE) {
                uint32_t e0 = (uint32_t)(m*NH + n);
                uint32_t e1 = (uint32_t)((m+8)*NH + n);
                __nv_bfloat162 h0, h1;
                h0.x = __float2bfloat16(tf_sample(k0, k1, e0,     p00));
                h0.y = __float2bfloat16(tf_sample(k0, k1, e0 + 1, p01));
                h1.x = __float2bfloat16(tf_sample(k0, k1, e1,     p10));
                h1.y = __float2bfloat16(tf_sample(k0, k1, e1 + 1, p11));
                *(__nv_bfloat162*)&H[(size_t)m*NH + n] = h0;
                *(__nv_bfloat162*)&H[(size_t)(m+8)*NH + n] = h1;
            } else {
                float2 r0 = { p00, p01 };
                float2 r1 = { p10, p11 };
                *(float2*)&C[(size_t)m*NH + n] = r0;
                *(float2*)&C[(size_t)(m+8)*NH + n] = r1;
            }
        }
    }
}

// ---------------- gw GEMM (split-K, deterministic partials) ----------------
__global__ __launch_bounds__(256) void gw_mma_kernel(
    const bf16* __restrict__ A0p, const bf16* __restrict__ A1p,
    const bf16* __restrict__ A2p, const bf16* __restrict__ A3p,
    const bf16* __restrict__ Bk, const bf16* __restrict__ B0,
    float* __restrict__ part)
{
    __shared__ __align__(16) bf16 sA[2][128*TSTRIDE];
    __shared__ __align__(16) bf16 sB[2][128*TSTRIDE];
    int m0 = blockIdx.x * 128;
    int n0 = blockIdx.y * 128;
    int ks = blockIdx.z;
    size_t kbase = (size_t)ks * (NB / GW_SPLITK);
    int tid = threadIdx.x;
    int warp = tid >> 5, lane = tid & 31;
    int wm = warp & 1, wn = warp >> 1;

    const bf16* Ap[4] = { A0p, A1p, A2p, A3p };
    const bf16* Bp[4] = { Bk, Bk, B0, B0 };

    float acc[4][4][4];
#pragma unroll
    for (int mi = 0; mi < 4; mi++)
#pragma unroll
        for (int ni = 0; ni < 4; ni++)
#pragma unroll
            for (int j = 0; j < 4; j++) acc[mi][ni][j] = 0.0f;

    const int NIT = 128;
    load_tile(sA[0], Ap[0] + (size_t)m0*NB + kbase, NB, tid);
    load_tile(sB[0], Bp[0] + (size_t)n0*NB + kbase, NB, tid);
    cpa_commit();

    for (int it = 0; it < NIT; it++) {
        int cur = it & 1;
        if (it + 1 < NIT) {
            int jt = it + 1;
            int p = jt >> 5;
            size_t k = kbase + (size_t)(jt & 31) * 32;
            load_tile(sA[cur^1], Ap[p] + (size_t)m0*NB + k, NB, tid);
            load_tile(sB[cur^1], Bp[p] + (size_t)n0*NB + k, NB, tid);
            cpa_commit();
            cpa_wait1();
        } else {
            cpa_wait0();
        }
        __syncthreads();
        mma_tile(sA[cur], sB[cur], wm, wn, lane, acc);
        __syncthreads();
    }

#pragma unroll
    for (int mi = 0; mi < 4; mi++) {
        int m = m0 + wm*64 + mi*16 + (lane>>2);
#pragma unroll
        for (int ni = 0; ni < 4; ni++) {
            int n = n0 + wn*32 + ni*8 + 2*(lane&3);
            float2 r0 = { acc[mi][ni][0], acc[mi][ni][1] };
            float2 r1 = { acc[mi][ni][2], acc[mi][ni][3] };
            *(float2*)&part[(size_t)ks*GW_ELEMS + (size_t)m*NV + n] = r0;
            *(float2*)&part[(size_t)ks*GW_ELEMS + (size_t)(m+8)*NV + n] = r1;
        }
    }
}

// ---------------- fused sparse h @ W + vb  ->  sample visible -> bf16 v ----------------
__global__ __launch_bounds__(256) void spmm_sample_kernel(
    const bf16* __restrict__ h, const float* __restrict__ Wm,
    const float* __restrict__ vb, bf16* __restrict__ vout,
    uint32_t k0, uint32_t k1)
{
    int warp = (blockIdx.x * blockDim.x + threadIdx.x) >> 5;
    int lane = threadIdx.x & 31;
    if (warp >= NB) return;
    const bf16* hr = h + (size_t)warp * NH;
    float acc[32];
#pragma unroll
    for (int t = 0; t < 32; t++) acc[t] = vb[t*32 + lane];
#pragma unroll
    for (int g = 0; g < 8; g++) {
        float hv = __bfloat162float(hr[g*32 + lane]);
        unsigned mask = __ballot_sync(0xffffffffu, hv != 0.0f);
        while (mask) {
            int bit = __ffs(mask) - 1; mask &= mask - 1;
            const float* wr = Wm + (size_t)(g*32 + bit) * NV;
#pragma unroll
            for (int t = 0; t < 32; t++) acc[t] += wr[t*32 + lane];
        }
    }
    uint32_t ebase = (uint32_t)warp * NV + lane;
    bf16* outp = vout + (size_t)warp * NV;
#pragma unroll
    for (int t = 0; t < 32; t++) {
        float s = tf_sample(k0, k1, ebase + t*32, acc[t]);
        outp[t*32 + lane] = __float2bfloat16(s);
    }
}

// ---------------- inv_norm (reads bf16 binary vk — exact) ----------------
__global__ __launch_bounds__(256) void invn_kernel(
    const float* __restrict__ prek, const bf16* __restrict__ vk,
    const float* __restrict__ vb, float* __restrict__ invn)
{
    int warp = (blockIdx.x * blockDim.x + threadIdx.x) >> 5;
    int lane = threadIdx.x & 31;
    if (warp >= NB) return;
    float s = 0.0f;
    const float* pr = prek + (size_t)warp * NH;
#pragma unroll
    for (int t = 0; t < 8; t++) {
        float x = pr[t*32 + lane];
        s += fmaxf(x, 0.0f) + log1pf(expf(-fabsf(x)));
    }
    const bf16* vr = vk + (size_t)warp * NV;
#pragma unroll
    for (int t = 0; t < 32; t++)
        s = fmaf(__bfloat162float(vr[t*32 + lane]), vb[t*32 + lane], s);
#pragma unroll
    for (int o = 16; o > 0; o >>= 1) s += __shfl_xor_sync(0xffffffffu, s, o);
    if (lane == 0) invn[warp] = expf(-s) * (1.0f / (float)NB);
}

// ---------------- a = invn[b] * sigmoid(pre), in place ----------------
__global__ __launch_bounds__(256) void atrans_kernel(
    float* __restrict__ a, const float* __restrict__ invn)
{
    int i = blockIdx.x * blockDim.x + threadIdx.x;
    if (i >= NB * NH) return;
    int b = i >> 8;
    a[i] = invn[b] * sigmoid_f(a[i]);
}

// ---------------- transpose + bf16 hi/lo split for a-matrices ----------------
__global__ __launch_bounds__(256) void trans_a_kernel(
    const float* __restrict__ src, float sign,
    bf16* __restrict__ dhi, bf16* __restrict__ dlo)
{
    __shared__ float t[32][33];
    int b0 = blockIdx.x * 32, h0 = blockIdx.y * 32;
    int tid = threadIdx.x;
#pragma unroll
    for (int i = 0; i < 4; i++) {
        int idx = tid + 256*i; int bl = idx >> 5, hl = idx & 31;
        t[hl][bl] = src[(size_t)(b0+bl)*NH + h0 + hl];
    }
    __syncthreads();
#pragma unroll
    for (int i = 0; i < 4; i++) {
        int idx = tid + 256*i; int hl = idx >> 5, bl = idx & 31;
        float v = sign * t[hl][bl];
        bf16 hi = __float2bfloat16(v);
        float lo = v - __bfloat162float(hi);
        size_t o = (size_t)(h0+hl)*NB + b0 + bl;
        dhi[o] = hi; dlo[o] = __float2bfloat16(lo);
    }
}

// bf16 [NB,NV] -> bf16 [NV,NB] transpose
__global__ __launch_bounds__(256) void trans_vbf_kernel(
    const bf16* __restrict__ src, bf16* __restrict__ dst)
{
    __shared__ uint16_t t[32][34];
    int b0 = blockIdx.x * 32, v0 = blockIdx.y * 32;
    int tid = threadIdx.x;
#pragma unroll
    for (int i = 0; i < 4; i++) {
        int idx = tid + 256*i; int bl = idx >> 5, vl = idx & 31;
        t[vl][bl] = ((const uint16_t*)src)[(size_t)(b0+bl)*NV + v0 + vl];
    }
    __syncthreads();
#pragma unroll
    for (int i = 0; i < 4; i++) {
        int idx = tid + 256*i; int vl = idx >> 5, bl = idx & 31;
        ((uint16_t*)dst)[(size_t)(v0+vl)*NB + b0 + bl] = t[vl][bl];
    }
}

// ---------------- W split, batch convert ----------------
__global__ __launch_bounds__(256) void wsplit_kernel(
    const float* __restrict__ W, bf16* __restrict__ whi, bf16* __restrict__ wlo)
{
    int i = blockIdx.x * 256 + threadIdx.x;
    if (i >= NH*NV) return;
    float w = W[i];
    bf16 hi = __float2bfloat16(w);
    whi[i] = hi;
    wlo[i] = __float2bfloat16(w - __bfloat162float(hi));
}

__global__ __launch_bounds__(256) void bconv_kernel(
    const float* __restrict__ src, bf16* __restrict__ dst, int n)
{
    int i = blockIdx.x * 256 + threadIdx.x;
    if (i < n) dst[i] = __float2bfloat16(src[i]);
}

// ---------------- g_vb / g_hb partials ----------------
__global__ __launch_bounds__(256) void vb_part_kernel(
    const bf16* __restrict__ vk, const bf16* __restrict__ v0,
    const float* __restrict__ invn, float* __restrict__ part)
{
    int v = blockIdx.x * 256 + threadIdx.x;
    int b0 = blockIdx.y * (NB / 32);
    float s = 0.0f;
    for (int b = b0; b < b0 + NB/32; b++) {
        float d = __bfloat162float(vk[(size_t)b*NV + v])
                - __bfloat162float(v0[(size_t)b*NV + v]);
        s = fmaf(invn[b], d, s);
    }
    part[blockIdx.y * NV + v] = s;
}

__global__ __launch_bounds__(256) void hb_part_kernel(
    const float* __restrict__ ak, const float* __restrict__ a0,
    float* __restrict__ part)
{
    int h = threadIdx.x;
    int b0 = blockIdx.x * (NB / 32);
    float s = 0.0f;
    for (int b = b0; b < b0 + NB/32; b++)
        s += ak[(size_t)b*NH + h] - a0[(size_t)b*NH + h];
    part[blockIdx.x * NH + h] = s;
}

// ---------------- finalize ----------------
__global__ __launch_bounds__(256) void finalize_kernel(
    const float* __restrict__ gw_part, const float* __restrict__ vb_part,
    const float* __restrict__ hb_part, float* __restrict__ out)
{
    int i = blockIdx.x * 256 + threadIdx.x;
    if (i < GW_ELEMS) {
        float s = 0.0f;
#pragma unroll
        for (int k = 0; k < GW_SPLITK; k++) s += gw_part[(size_t)k*GW_ELEMS + i];
        out[i] = s;
    } else if (i < OUT_HB_OFF) {
        int v = i - OUT_VB_OFF;
        float s = 0.0f;
#pragma unroll
        for (int k = 0; k < 32; k++) s += vb_part[k*NV + v];
        out[i] = s;
    } else if (i < OUT_TOTAL) {
        int h = i - OUT_HB_OFF;
        float s = 0.0f;
#pragma unroll
        for (int k = 0; k < 32; k++) s += hb_part[k*NH + h];
        out[i] = s;
    }
}

// ---------------- launch ----------------
extern "C" void kernel_launch(void* const* d_in, const int* in_sizes, int n_in,
                              void* d_out, int out_size)
{
    (void)in_sizes; (void)n_in; (void)out_size;
    const float* batch = (const float*)d_in[0];
    const float* W     = (const float*)d_in[1];
    const float* vb    = (const float*)d_in[2];
    const float* hb    = (const float*)d_in[3];
    float* out = (float*)d_out;

    float *ppreh, *ppreh0, *pinvn, *pgw, *pvbp, *phbp;
    bf16 *pvbf, *pbbf, *phbf, *pwhi, *pwlo, *pakhi, *paklo, *pna0hi, *pna0lo, *pvkT, *pv0T;
    cudaGetSymbolAddress((void**)&pvbf,   g_vbf);
    cudaGetSymbolAddress((void**)&pbbf,   g_batchbf);
    cudaGetSymbolAddress((void**)&phbf,   g_hbf);
    cudaGetSymbolAddress((void**)&ppreh,  g_preh);
    cudaGetSymbolAddress((void**)&ppreh0, g_preh0);
    cudaGetSymbolAddress((void**)&pinvn,  g_invn);
    cudaGetSymbolAddress((void**)&pwhi,   g_whi);
    cudaGetSymbolAddress((void**)&pwlo,   g_wlo);
    cudaGetSymbolAddress((void**)&pakhi,  g_akT_hi);
    cudaGetSymbolAddress((void**)&paklo,  g_akT_lo);
    cudaGetSymbolAddress((void**)&pna0hi, g_na0T_hi);
    cudaGetSymbolAddress((void**)&pna0lo, g_na0T_lo);
    cudaGetSymbolAddress((void**)&pvkT,   g_vkT);
    cudaGetSymbolAddress((void**)&pv0T,   g_v0T);
    cudaGetSymbolAddress((void**)&pgw,    g_gw_part);
    cudaGetSymbolAddress((void**)&pvbp,   g_vb_part);
    cudaGetSymbolAddress((void**)&phbp,   g_hb_part);

    // JAX partitionable split: key_m = threefry2x32((0,42), 0, m)
    uint32_t keys[16][2];
    for (int m = 0; m < 16; m++) {
        uint32_t o0, o1;
        threefry2x32(0u, 42u, 0u, (uint32_t)m, o0, o1);
        keys[m][0] = o0; keys[m][1] = o1;
    }

    const int totV = NB*NV;
    dim3 fgrid(NB/128, NH/128);   // (128, 2)

    wsplit_kernel<<<(NH*NV + 255)/256, 256>>>(W, pwhi, pwlo);
    bconv_kernel<<<(totV + 255)/256, 256>>>(batch, pbbf, totV);

    for (int s = 0; s < KSTEPS; s++) {
        const bf16* Ain = (s == 0) ? pbbf : pvbf;
        fgemm_kernel<true><<<fgrid, 256>>>(Ain, pwhi, pwlo, hb,
                                           (float*)nullptr, phbf,
                                           keys[2*s][0], keys[2*s][1]);
        spmm_sample_kernel<<<NB/8, 256>>>(phbf, W, vb, pvbf,
                                          keys[2*s+1][0], keys[2*s+1][1]);
    }

    fgemm_kernel<false><<<fgrid, 256>>>(pvbf, pwhi, pwlo, hb, ppreh,  (bf16*)nullptr, 0u, 0u);
    fgemm_kernel<false><<<fgrid, 256>>>(pbbf, pwhi, pwlo, hb, ppreh0, (bf16*)nullptr, 0u, 0u);
    invn_kernel<<<NB/8, 256>>>(ppreh, pvbf, vb, pinvn);
    atrans_kernel<<<NB*NH/256, 256>>>(ppreh,  pinvn);   // a_k
    atrans_kernel<<<NB*NH/256, 256>>>(ppreh0, pinvn);   // a_0

    trans_a_kernel<<<dim3(NB/32, NH/32), 256>>>(ppreh,  1.0f, pakhi, paklo);
    trans_a_kernel<<<dim3(NB/32, NH/32), 256>>>(ppreh0, -1.0f, pna0hi, pna0lo);
    trans_vbf_kernel<<<dim3(NB/32, NV/32), 256>>>(pvbf, pvkT);
    trans_vbf_kernel<<<dim3(NB/32, NV/32), 256>>>(pbbf, pv0T);

    gw_mma_kernel<<<dim3(NH/128, NV/128, GW_SPLITK), 256>>>(
        pakhi, paklo, pna0hi, pna0lo, pvkT, pv0T, pgw);

    vb_part_kernel<<<dim3(NV/256, 32), 256>>>(pvbf, pbbf, pinvn, pvbp);
    hb_part_kernel<<<32, 256>>>(ppreh, ppreh0, phbp);
    finalize_kernel<<<(OUT_TOTAL + 255)/256, 256>>>(pgw, pvbp, phbp, out);
}

// round 10
// speedup vs baseline: 2.4560x; 1.1798x over previous
#include <cuda_runtime.h>
#include <cuda_bf16.h>
#include <cstdint>
#include <cstddef>

#define NB 16384
#define NV 1024
#define NH 256
#define KSTEPS 8
#define GW_ELEMS (NH*NV)          // 262144
#define OUT_VB_OFF GW_ELEMS
#define OUT_HB_OFF (GW_ELEMS+NV)
#define OUT_TOTAL (GW_ELEMS+NV+NH)
#define GW_SPLITK 16

typedef __nv_bfloat16 bf16;

// ---------------- static scratch ----------------
__device__ bf16  g_vbf[NB*NV];      // current visible state, bf16 (binary, exact)
__device__ bf16  g_batchbf[NB*NV];
__device__ bf16  g_hbf[NB*NH];      // hidden state, bf16 (binary, exact)
__device__ float g_preh[NB*NH];     // pre_k
__device__ float g_preh0[NB*NH];    // pre0
__device__ float g_invn[NB];
__device__ bf16  g_whi[NH*NV];
__device__ bf16  g_wlo[NH*NV];
__device__ bf16  g_akT_hi[NH*NB];
__device__ bf16  g_akT_lo[NH*NB];
__device__ bf16  g_na0T_hi[NH*NB];
__device__ bf16  g_na0T_lo[NH*NB];
__device__ bf16  g_vkT[NV*NB];
__device__ bf16  g_v0T[NV*NB];
__device__ float g_gw_part[GW_SPLITK*GW_ELEMS];
__device__ float g_vb_part[32*NV];
__device__ float g_hb_part[32*NH];

// ---------------- threefry2x32 (JAX partitionable) ----------------
__host__ __device__ __forceinline__ void threefry2x32(
    uint32_t k0, uint32_t k1, uint32_t c0, uint32_t c1,
    uint32_t& o0, uint32_t& o1)
{
    uint32_t k2 = k0 ^ k1 ^ 0x1BD11BDAu;
    uint32_t x0 = c0 + k0, x1 = c1 + k1;
#define TF_R(r) { x0 += x1; x1 = (x1 << (r)) | (x1 >> (32 - (r))); x1 ^= x0; }
    TF_R(13) TF_R(15) TF_R(26) TF_R(6)
    x0 += k1; x1 += k2 + 1u;
    TF_R(17) TF_R(29) TF_R(16) TF_R(24)
    x0 += k2; x1 += k0 + 2u;
    TF_R(13) TF_R(15) TF_R(26) TF_R(6)
    x0 += k0; x1 += k1 + 3u;
    TF_R(17) TF_R(29) TF_R(16) TF_R(24)
    x0 += k1; x1 += k2 + 4u;
    TF_R(13) TF_R(15) TF_R(26) TF_R(6)
    x0 += k2; x1 += k0 + 5u;
#undef TF_R
    o0 = x0; o1 = x1;
}

__device__ __forceinline__ float tf_uniform(uint32_t bits) {
    return __uint_as_float((bits >> 9) | 0x3f800000u) - 1.0f;
}
__device__ __forceinline__ float sigmoid_f(float x) {
    return 1.0f / (1.0f + expf(-x));
}
__device__ __forceinline__ float tf_sample(uint32_t k0, uint32_t k1, uint32_t e, float pre) {
    uint32_t o0, o1;
    threefry2x32(k0, k1, 0u, e, o0, o1);
    return (tf_uniform(o0 ^ o1) < sigmoid_f(pre)) ? 1.0f : 0.0f;
}

// ---------------- cp.async / ldmatrix / mma helpers ----------------
__device__ __forceinline__ void cpa16(void* s, const void* g) {
    uint32_t sa = (uint32_t)__cvta_generic_to_shared(s);
    asm volatile("cp.async.ca.shared.global [%0], [%1], 16;\n" :: "r"(sa), "l"(g));
}
__device__ __forceinline__ void cpa_commit() {
    asm volatile("cp.async.commit_group;\n" ::);
}
__device__ __forceinline__ void cpa_wait1() {
    asm volatile("cp.async.wait_group 1;\n" ::);
}
__device__ __forceinline__ void cpa_wait0() {
    asm volatile("cp.async.wait_group 0;\n" ::);
}
__device__ __forceinline__ void ldsm4(uint32_t& r0, uint32_t& r1, uint32_t& r2, uint32_t& r3,
                                      uint32_t addr) {
    asm volatile("ldmatrix.sync.aligned.m8n8.x4.shared.b16 {%0,%1,%2,%3}, [%4];\n"
                 : "=r"(r0), "=r"(r1), "=r"(r2), "=r"(r3) : "r"(addr));
}
__device__ __forceinline__ void mma16816(float* c, const uint32_t* a, const uint32_t* b) {
    asm volatile(
        "mma.sync.aligned.m16n8k16.row.col.f32.bf16.bf16.f32 "
        "{%0,%1,%2,%3}, {%4,%5,%6,%7}, {%8,%9}, {%0,%1,%2,%3};\n"
        : "+f"(c[0]), "+f"(c[1]), "+f"(c[2]), "+f"(c[3])
        : "r"(a[0]), "r"(a[1]), "r"(a[2]), "r"(a[3]), "r"(b[0]), "r"(b[1]));
}

// SMEM tile: 128 rows x 32 bf16, row stride 40 bf16 (80B: 16B-aligned, LDSM conflict-free)
#define TSTRIDE 40
#define STAGE_ELE (128*TSTRIDE)           // bf16 elems per matrix per stage
#define STAGE_BYTES (2*STAGE_ELE*2)       // A+B per stage, bytes (20480)
#define SMEM_TOTAL_BYTES (3*STAGE_BYTES)  // 61440

__device__ __forceinline__ void load_tile(bf16* s, const bf16* g, size_t ldg, int tid) {
#pragma unroll
    for (int i = 0; i < 2; i++) {
        int c = tid + 256*i;
        int row = c >> 2, w = c & 3;
        cpa16(s + row*TSTRIDE + w*8, g + (size_t)row*ldg + w*8);
    }
}

// ldmatrix-based compute of one 128x128x32 tile. Same kk/mi/ni order as before
// (bit-identical accumulation).
__device__ __forceinline__ void mma_tile_ldsm(uint32_t aBase, uint32_t bBase,
                                              int wm, int wn, int lane, float acc[4][4][4]) {
    int lr = lane & 15;
    int kadd = (lane >> 4) * 8;
#pragma unroll
    for (int kk = 0; kk < 32; kk += 16) {
        uint32_t a[4][4], b[4][2];
#pragma unroll
        for (int mi = 0; mi < 4; mi++) {
            uint32_t addr = aBase + (uint32_t)(((wm*64 + mi*16 + lr)*TSTRIDE + kk + kadd) * 2);
            ldsm4(a[mi][0], a[mi][1], a[mi][2], a[mi][3], addr);
        }
#pragma unroll
        for (int np = 0; np < 2; np++) {
            uint32_t addr = bBase + (uint32_t)(((wn*32 + np*16 + lr)*TSTRIDE + kk + kadd) * 2);
            uint32_t r0, r1, r2, r3;
            ldsm4(r0, r1, r2, r3, addr);
            b[np*2][0]   = r0;
            b[np*2+1][0] = r1;
            b[np*2][1]   = r2;
            b[np*2+1][1] = r3;
        }
#pragma unroll
        for (int mi = 0; mi < 4; mi++)
#pragma unroll
            for (int ni = 0; ni < 4; ni++)
                mma16816(acc[mi][ni], a[mi], b[ni]);
    }
}

// ---------------- forward GEMM: pre[M,NH] = v[M,NV] @ (Whi|Wlo)^T + hb ----------------
// 3-stage cp.async pipeline, one __syncthreads per iteration.
template<bool SAMPLE>
__global__ __launch_bounds__(256) void fgemm_kernel(
    const bf16* __restrict__ A, const bf16* __restrict__ Whi,
    const bf16* __restrict__ Wlo, const float* __restrict__ bias,
    float* __restrict__ C, bf16* __restrict__ H,
    uint32_t k0, uint32_t k1)
{
    extern __shared__ __align__(16) bf16 dsm[];
    int m0 = blockIdx.x * 128;
    int n0 = blockIdx.y * 128;
    int tid = threadIdx.x;
    int warp = tid >> 5, lane = tid & 31;
    int wm = warp & 1, wn = warp >> 1;
    uint32_t sbase = (uint32_t)__cvta_generic_to_shared(dsm);

    float acc[4][4][4];
#pragma unroll
    for (int mi = 0; mi < 4; mi++)
#pragma unroll
        for (int ni = 0; ni < 4; ni++)
#pragma unroll
            for (int j = 0; j < 4; j++) acc[mi][ni][j] = 0.0f;

    const int NIT = 64;
    // prologue: stages 0,1
#pragma unroll
    for (int jt = 0; jt < 2; jt++) {
        bf16* sA = dsm + jt*(2*STAGE_ELE);
        bf16* sB = sA + STAGE_ELE;
        int k = (jt & 31) * 32;
        load_tile(sA, A + (size_t)m0*NV + k, NV, tid);
        load_tile(sB, Whi + (size_t)n0*NV + k, NV, tid);
        cpa_commit();
    }

    for (int it = 0; it < NIT; it++) {
        if (it == NIT-1) cpa_wait0(); else cpa_wait1();
        __syncthreads();
        if (it + 2 < NIT) {
            int jt = it + 2;
            int st = jt % 3;
            int k = (jt & 31) * 32;
            const bf16* Bp = (jt < 32) ? Whi : Wlo;
            bf16* sA = dsm + st*(2*STAGE_ELE);
            load_tile(sA, A + (size_t)m0*NV + k, NV, tid);
            load_tile(sA + STAGE_ELE, Bp + (size_t)n0*NV + k, NV, tid);
            cpa_commit();
        }
        int st = it % 3;
        uint32_t aB = sbase + st*STAGE_BYTES;
        mma_tile_ldsm(aB, aB + STAGE_ELE*2, wm, wn, lane, acc);
    }

#pragma unroll
    for (int mi = 0; mi < 4; mi++) {
        int m = m0 + wm*64 + mi*16 + (lane>>2);
#pragma unroll
        for (int ni = 0; ni < 4; ni++) {
            int n = n0 + wn*32 + ni*8 + 2*(lane&3);
            float2 b2 = *(const float2*)&bias[n];
            float p00 = acc[mi][ni][0] + b2.x;
            float p01 = acc[mi][ni][1] + b2.y;
            float p10 = acc[mi][ni][2] + b2.x;
            float p11 = acc[mi][ni][3] + b2.y;
            if (SAMPLE) {
                uint32_t e0 = (uint32_t)(m*NH + n);
                uint32_t e1 = (uint32_t)((m+8)*NH + n);
                __nv_bfloat162 h0, h1;
                h0.x = __float2bfloat16(tf_sample(k0, k1, e0,     p00));
                h0.y = __float2bfloat16(tf_sample(k0, k1, e0 + 1, p01));
                h1.x = __float2bfloat16(tf_sample(k0, k1, e1,     p10));
                h1.y = __float2bfloat16(tf_sample(k0, k1, e1 + 1, p11));
                *(__nv_bfloat162*)&H[(size_t)m*NH + n] = h0;
                *(__nv_bfloat162*)&H[(size_t)(m+8)*NH + n] = h1;
            } else {
                float2 r0 = { p00, p01 };
                float2 r1 = { p10, p11 };
                *(float2*)&C[(size_t)m*NH + n] = r0;
                *(float2*)&C[(size_t)(m+8)*NH + n] = r1;
            }
        }
    }
}

// ---------------- gw GEMM (split-K, deterministic partials) ----------------
__global__ __launch_bounds__(256) void gw_mma_kernel(
    const bf16* __restrict__ A0p, const bf16* __restrict__ A1p,
    const bf16* __restrict__ A2p, const bf16* __restrict__ A3p,
    const bf16* __restrict__ Bk, const bf16* __restrict__ B0,
    float* __restrict__ part)
{
    extern __shared__ __align__(16) bf16 dsm[];
    int m0 = blockIdx.x * 128;
    int n0 = blockIdx.y * 128;
    int ks = blockIdx.z;
    size_t kbase = (size_t)ks * (NB / GW_SPLITK);
    int tid = threadIdx.x;
    int warp = tid >> 5, lane = tid & 31;
    int wm = warp & 1, wn = warp >> 1;
    uint32_t sbase = (uint32_t)__cvta_generic_to_shared(dsm);

    const bf16* Ap[4] = { A0p, A1p, A2p, A3p };
    const bf16* Bp[4] = { Bk, Bk, B0, B0 };

    float acc[4][4][4];
#pragma unroll
    for (int mi = 0; mi < 4; mi++)
#pragma unroll
        for (int ni = 0; ni < 4; ni++)
#pragma unroll
            for (int j = 0; j < 4; j++) acc[mi][ni][j] = 0.0f;

    const int NIT = 128;
#pragma unroll
    for (int jt = 0; jt < 2; jt++) {
        bf16* sA = dsm + jt*(2*STAGE_ELE);
        size_t k = kbase + (size_t)(jt & 31) * 32;
        load_tile(sA, Ap[0] + (size_t)m0*NB + k, NB, tid);
        load_tile(sA + STAGE_ELE, Bp[0] + (size_t)n0*NB + k, NB, tid);
        cpa_commit();
    }

    for (int it = 0; it < NIT; it++) {
        if (it == NIT-1) cpa_wait0(); else cpa_wait1();
        __syncthreads();
        if (it + 2 < NIT) {
            int jt = it + 2;
            int st = jt % 3;
            int p = jt >> 5;
            size_t k = kbase + (size_t)(jt & 31) * 32;
            bf16* sA = dsm + st*(2*STAGE_ELE);
            load_tile(sA, Ap[p] + (size_t)m0*NB + k, NB, tid);
            load_tile(sA + STAGE_ELE, Bp[p] + (size_t)n0*NB + k, NB, tid);
            cpa_commit();
        }
        int st = it % 3;
        uint32_t aB = sbase + st*STAGE_BYTES;
        mma_tile_ldsm(aB, aB + STAGE_ELE*2, wm, wn, lane, acc);
    }

#pragma unroll
    for (int mi = 0; mi < 4; mi++) {
        int m = m0 + wm*64 + mi*16 + (lane>>2);
#pragma unroll
        for (int ni = 0; ni < 4; ni++) {
            int n = n0 + wn*32 + ni*8 + 2*(lane&3);
            float2 r0 = { acc[mi][ni][0], acc[mi][ni][1] };
            float2 r1 = { acc[mi][ni][2], acc[mi][ni][3] };
            *(float2*)&part[(size_t)ks*GW_ELEMS + (size_t)m*NV + n] = r0;
            *(float2*)&part[(size_t)ks*GW_ELEMS + (size_t)(m+8)*NV + n] = r1;
        }
    }
}

// ---------------- fused sparse h @ W + vb -> sample visible -> bf16 v ----------------
// 2 warps per sample: warp half 0 -> cols [0,512), half 1 -> [512,1024)
__global__ __launch_bounds__(256) void spmm_sample_kernel(
    const bf16* __restrict__ h, const float* __restrict__ Wm,
    const float* __restrict__ vb, bf16* __restrict__ vout,
    uint32_t k0, uint32_t k1)
{
    int tid = threadIdx.x;
    int lane = tid & 31;
    int half = (tid >> 5) & 1;
    int sample = blockIdx.x * 4 + (tid >> 6);
    int cbase = half * 512 + lane;

    const bf16* hr = h + (size_t)sample * NH;
    float acc[16];
#pragma unroll
    for (int t = 0; t < 16; t++) acc[t] = vb[cbase + t*32];
#pragma unroll
    for (int g = 0; g < 8; g++) {
        float hv = __bfloat162float(hr[g*32 + lane]);
        unsigned mask = __ballot_sync(0xffffffffu, hv != 0.0f);
        while (mask) {
            int bit = __ffs(mask) - 1; mask &= mask - 1;
            const float* wr = Wm + (size_t)(g*32 + bit) * NV + cbase;
#pragma unroll
            for (int t = 0; t < 16; t++) acc[t] += wr[t*32];
        }
    }
    uint32_t ebase = (uint32_t)sample * NV + cbase;
    bf16* outp = vout + (size_t)sample * NV + cbase;
#pragma unroll
    for (int t = 0; t < 16; t++) {
        float s = tf_sample(k0, k1, ebase + t*32, acc[t]);
        outp[t*32] = __float2bfloat16(s);
    }
}

// ---------------- inv_norm ----------------
__global__ __launch_bounds__(256) void invn_kernel(
    const float* __restrict__ prek, const bf16* __restrict__ vk,
    const float* __restrict__ vb, float* __restrict__ invn)
{
    int warp = (blockIdx.x * blockDim.x + threadIdx.x) >> 5;
    int lane = threadIdx.x & 31;
    if (warp >= NB) return;
    float s = 0.0f;
    const float* pr = prek + (size_t)warp * NH;
#pragma unroll
    for (int t = 0; t < 8; t++) {
        float x = pr[t*32 + lane];
        s += fmaxf(x, 0.0f) + log1pf(expf(-fabsf(x)));
    }
    const bf16* vr = vk + (size_t)warp * NV;
#pragma unroll
    for (int t = 0; t < 32; t++)
        s = fmaf(__bfloat162float(vr[t*32 + lane]), vb[t*32 + lane], s);
#pragma unroll
    for (int o = 16; o > 0; o >>= 1) s += __shfl_xor_sync(0xffffffffu, s, o);
    if (lane == 0) invn[warp] = expf(-s) * (1.0f / (float)NB);
}

// ---------------- fused: a = sign*invn*sigmoid(pre), transpose + hi/lo split ----------
__global__ __launch_bounds__(256) void trans_a_kernel(
    const float* __restrict__ src, const float* __restrict__ invn, float sign,
    bf16* __restrict__ dhi, bf16* __restrict__ dlo)
{
    __shared__ float t[32][33];
    int b0 = blockIdx.x * 32, h0 = blockIdx.y * 32;
    int tid = threadIdx.x;
#pragma unroll
    for (int i = 0; i < 4; i++) {
        int idx = tid + 256*i; int bl = idx >> 5, hl = idx & 31;
        float pre = src[(size_t)(b0+bl)*NH + h0 + hl];
        t[hl][bl] = invn[b0+bl] * sigmoid_f(pre);
    }
    __syncthreads();
#pragma unroll
    for (int i = 0; i < 4; i++) {
        int idx = tid + 256*i; int hl = idx >> 5, bl = idx & 31;
        float v = sign * t[hl][bl];
        bf16 hi = __float2bfloat16(v);
        float lo = v - __bfloat162float(hi);
        size_t o = (size_t)(h0+hl)*NB + b0 + bl;
        dhi[o] = hi; dlo[o] = __float2bfloat16(lo);
    }
}

// bf16 [NB,NV] -> bf16 [NV,NB] transpose
__global__ __launch_bounds__(256) void trans_vbf_kernel(
    const bf16* __restrict__ src, bf16* __restrict__ dst)
{
    __shared__ uint16_t t[32][34];
    int b0 = blockIdx.x * 32, v0 = blockIdx.y * 32;
    int tid = threadIdx.x;
#pragma unroll
    for (int i = 0; i < 4; i++) {
        int idx = tid + 256*i; int bl = idx >> 5, vl = idx & 31;
        t[vl][bl] = ((const uint16_t*)src)[(size_t)(b0+bl)*NV + v0 + vl];
    }
    __syncthreads();
#pragma unroll
    for (int i = 0; i < 4; i++) {
        int idx = tid + 256*i; int vl = idx >> 5, bl = idx & 31;
        ((uint16_t*)dst)[(size_t)(v0+vl)*NB + b0 + bl] = t[vl][bl];
    }
}

// ---------------- W split, batch convert ----------------
__global__ __launch_bounds__(256) void wsplit_kernel(
    const float* __restrict__ W, bf16* __restrict__ whi, bf16* __restrict__ wlo)
{
    int i = blockIdx.x * 256 + threadIdx.x;
    if (i >= NH*NV) return;
    float w = W[i];
    bf16 hi = __float2bfloat16(w);
    whi[i] = hi;
    wlo[i] = __float2bfloat16(w - __bfloat162float(hi));
}

__global__ __launch_bounds__(256) void bconv_kernel(
    const float* __restrict__ src, bf16* __restrict__ dst, int n)
{
    int i = blockIdx.x * 256 + threadIdx.x;
    if (i < n) dst[i] = __float2bfloat16(src[i]);
}

// ---------------- g_vb / g_hb partials ----------------
__global__ __launch_bounds__(256) void vb_part_kernel(
    const bf16* __restrict__ vk, const bf16* __restrict__ v0,
    const float* __restrict__ invn, float* __restrict__ part)
{
    int v = blockIdx.x * 256 + threadIdx.x;
    int b0 = blockIdx.y * (NB / 32);
    float s = 0.0f;
    for (int b = b0; b < b0 + NB/32; b++) {
        float d = __bfloat162float(vk[(size_t)b*NV + v])
                - __bfloat162float(v0[(size_t)b*NV + v]);
        s = fmaf(invn[b], d, s);
    }
    part[blockIdx.y * NV + v] = s;
}

// hb partials from transposed hi/lo arrays: sum over b of (ak + (-a0))
// grid (NH/8, 32); warp w -> h = bx*8+w, chunk = by*512
__global__ __launch_bounds__(256) void hb_part_kernel(
    const bf16* __restrict__ akhi, const bf16* __restrict__ aklo,
    const bf16* __restrict__ nahi, const bf16* __restrict__ nalo,
    float* __restrict__ part)
{
    int w = threadIdx.x >> 5, lane = threadIdx.x & 31;
    int h = blockIdx.x * 8 + w;
    int b0 = blockIdx.y * 512;
    size_t base = (size_t)h*NB + b0 + lane;
    float s = 0.0f;
#pragma unroll
    for (int j = 0; j < 16; j++) {
        size_t o = base + j*32;
        s += __bfloat162float(akhi[o]) + __bfloat162float(aklo[o])
           + __bfloat162float(nahi[o]) + __bfloat162float(nalo[o]);
    }
#pragma unroll
    for (int o = 16; o > 0; o >>= 1) s += __shfl_xor_sync(0xffffffffu, s, o);
    if (lane == 0) part[blockIdx.y * NH + h] = s;
}

// ---------------- finalize ----------------
__global__ __launch_bounds__(256) void finalize_kernel(
    const float* __restrict__ gw_part, const float* __restrict__ vb_part,
    const float* __restrict__ hb_part, float* __restrict__ out)
{
    int i = blockIdx.x * 256 + threadIdx.x;
    if (i < GW_ELEMS) {
        float s = 0.0f;
#pragma unroll
        for (int k = 0; k < GW_SPLITK; k++) s += gw_part[(size_t)k*GW_ELEMS + i];
        out[i] = s;
    } else if (i < OUT_HB_OFF) {
        int v = i - OUT_VB_OFF;
        float s = 0.0f;
#pragma unroll
        for (int k = 0; k < 32; k++) s += vb_part[k*NV + v];
        out[i] = s;
    } else if (i < OUT_TOTAL) {
        int h = i - OUT_HB_OFF;
        float s = 0.0f;
#pragma unroll
        for (int k = 0; k < 32; k++) s += hb_part[k*NH + h];
        out[i] = s;
    }
}

// ---------------- launch ----------------
extern "C" void kernel_launch(void* const* d_in, const int* in_sizes, int n_in,
                              void* d_out, int out_size)
{
    (void)in_sizes; (void)n_in; (void)out_size;
    const float* batch = (const float*)d_in[0];
    const float* W     = (const float*)d_in[1];
    const float* vb    = (const float*)d_in[2];
    const float* hb    = (const float*)d_in[3];
    float* out = (float*)d_out;

    float *ppreh, *ppreh0, *pinvn, *pgw, *pvbp, *phbp;
    bf16 *pvbf, *pbbf, *phbf, *pwhi, *pwlo, *pakhi, *paklo, *pna0hi, *pna0lo, *pvkT, *pv0T;
    cudaGetSymbolAddress((void**)&pvbf,   g_vbf);
    cudaGetSymbolAddress((void**)&pbbf,   g_batchbf);
    cudaGetSymbolAddress((void**)&phbf,   g_hbf);
    cudaGetSymbolAddress((void**)&ppreh,  g_preh);
    cudaGetSymbolAddress((void**)&ppreh0, g_preh0);
    cudaGetSymbolAddress((void**)&pinvn,  g_invn);
    cudaGetSymbolAddress((void**)&pwhi,   g_whi);
    cudaGetSymbolAddress((void**)&pwlo,   g_wlo);
    cudaGetSymbolAddress((void**)&pakhi,  g_akT_hi);
    cudaGetSymbolAddress((void**)&paklo,  g_akT_lo);
    cudaGetSymbolAddress((void**)&pna0hi, g_na0T_hi);
    cudaGetSymbolAddress((void**)&pna0lo, g_na0T_lo);
    cudaGetSymbolAddress((void**)&pvkT,   g_vkT);
    cudaGetSymbolAddress((void**)&pv0T,   g_v0T);
    cudaGetSymbolAddress((void**)&pgw,    g_gw_part);
    cudaGetSymbolAddress((void**)&pvbp,   g_vb_part);
    cudaGetSymbolAddress((void**)&phbp,   g_hb_part);

    // allow 60KB dynamic smem (idempotent; not an allocation)
    cudaFuncSetAttribute(fgemm_kernel<true>,
        cudaFuncAttributeMaxDynamicSharedMemorySize, SMEM_TOTAL_BYTES);
    cudaFuncSetAttribute(fgemm_kernel<false>,
        cudaFuncAttributeMaxDynamicSharedMemorySize, SMEM_TOTAL_BYTES);
    cudaFuncSetAttribute(gw_mma_kernel,
        cudaFuncAttributeMaxDynamicSharedMemorySize, SMEM_TOTAL_BYTES);

    // JAX partitionable split: key_m = threefry2x32((0,42), 0, m)
    uint32_t keys[16][2];
    for (int m = 0; m < 16; m++) {
        uint32_t o0, o1;
        threefry2x32(0u, 42u, 0u, (uint32_t)m, o0, o1);
        keys[m][0] = o0; keys[m][1] = o1;
    }

    const int totV = NB*NV;
    dim3 fgrid(NB/128, NH/128);   // (128, 2)

    wsplit_kernel<<<(NH*NV + 255)/256, 256>>>(W, pwhi, pwlo);
    bconv_kernel<<<(totV + 255)/256, 256>>>(batch, pbbf, totV);

    for (int s = 0; s < KSTEPS; s++) {
        const bf16* Ain = (s == 0) ? pbbf : pvbf;
        fgemm_kernel<true><<<fgrid, 256, SMEM_TOTAL_BYTES>>>(Ain, pwhi, pwlo, hb,
                                           (float*)nullptr, phbf,
                                           keys[2*s][0], keys[2*s][1]);
        spmm_sample_kernel<<<NB/4, 256>>>(phbf, W, vb, pvbf,
                                          keys[2*s+1][0], keys[2*s+1][1]);
    }

    fgemm_kernel<false><<<fgrid, 256, SMEM_TOTAL_BYTES>>>(pvbf, pwhi, pwlo, hb,
                                        ppreh,  (bf16*)nullptr, 0u, 0u);
    fgemm_kernel<false><<<fgrid, 256, SMEM_TOTAL_BYTES>>>(pbbf, pwhi, pwlo, hb,
                                        ppreh0, (bf16*)nullptr, 0u, 0u);
    invn_kernel<<<NB/8, 256>>>(ppreh, pvbf, vb, pinvn);

    trans_a_kernel<<<dim3(NB/32, NH/32), 256>>>(ppreh,  pinvn,  1.0f, pakhi, paklo);
    trans_a_kernel<<<dim3(NB/32, NH/32), 256>>>(ppreh0, pinvn, -1.0f, pna0hi, pna0lo);
    trans_vbf_kernel<<<dim3(NB/32, NV/32), 256>>>(pvbf, pvkT);
    trans_vbf_kernel<<<dim3(NB/32, NV/32), 256>>>(pbbf, pv0T);

    gw_mma_kernel<<<dim3(NH/128, NV/128, GW_SPLITK), 256, SMEM_TOTAL_BYTES>>>(
        pakhi, paklo, pna0hi, pna0lo, pvkT, pv0T, pgw);

    vb_part_kernel<<<dim3(NV/256, 32), 256>>>(pvbf, pbbf, pinvn, pvbp);
    hb_part_kernel<<<dim3(NH/8, 32), 256>>>(pakhi, paklo, pna0hi, pna0lo, phbp);
    finalize_kernel<<<(OUT_TOTAL + 255)/256, 256>>>(pgw, pvbp, phbp, out);
}